// round 15
// baseline (speedup 1.0000x reference)
#include <cuda_runtime.h>
#include <cuda_fp16.h>
#include <math.h>

#define Bb 4
#define Nn 20000
#define Uu 64
#define Ff 65
#define Ee 640000
#define NODES (Bb*Nn)
#define ATT_SCALE 0.125f
#define FPH 68         // padded weight row stride (halves), gru
#define XS 36          // f-major x row stride (floats), gru
#define AS 88          // qkv: sA row stride in halves (conflict-free for frags)

typedef unsigned long long ull;

__device__ __forceinline__ ull pack2(float v) {
    ull r; asm("mov.b64 %0, {%1, %1};" : "=l"(r) : "f"(v)); return r;
}
__device__ __forceinline__ void fma2(ull &acc, ull x, ull w) {
    asm("fma.rn.f32x2 %0, %1, %2, %0;" : "+l"(acc) : "l"(x), "l"(w));
}
__device__ __forceinline__ float2 unpack2(ull v) {
    float2 f; asm("mov.b64 {%0, %1}, %2;" : "=f"(f.x), "=f"(f.y) : "l"(v)); return f;
}

// ---------------- device scratch (static, no runtime alloc) ----------------
__device__ __align__(16) __half g_qh[NODES*Uu];   // prescaled by ATT_SCALE
__device__ __align__(16) __half g_kh[NODES*Uu];
__device__ __align__(16) __half g_vh[NODES*Uu];
__device__ __align__(16) float  g_s[NODES*Uu];    // x@Ws + bs (fp32)
__device__ __align__(16) float  g_agg[NODES*Uu];  // h2 for masked nodes
__device__ unsigned char g_mask[NODES];
__device__ int g_cnt[Nn];
__device__ int g_off[Nn];
__device__ int g_cur[Nn];
__device__ int g_srt[Ee];   // src ids sorted by dst (CSR payload)

// ---------------- CSR build ----------------
__global__ void hist_kernel(const int* __restrict__ edst) {
    int i = blockIdx.x * blockDim.x + threadIdx.x;
    if (i < Ee/4) {
        int4 d = ((const int4*)edst)[i];
        atomicAdd(&g_cnt[d.x], 1);
        atomicAdd(&g_cnt[d.y], 1);
        atomicAdd(&g_cnt[d.z], 1);
        atomicAdd(&g_cnt[d.w], 1);
    }
}

__global__ void scan_kernel() {
    __shared__ int sp[1024];
    int tid = threadIdx.x;
    int base = tid * 20;
    int s = 0;
    #pragma unroll
    for (int i = 0; i < 20; i++) {
        int idx = base + i;
        if (idx < Nn) s += g_cnt[idx];
    }
    sp[tid] = s;
    __syncthreads();
    for (int d = 1; d < 1024; d <<= 1) {
        int v = (tid >= d) ? sp[tid - d] : 0;
        __syncthreads();
        sp[tid] += v;
        __syncthreads();
    }
    int run = sp[tid] - s;   // exclusive prefix
    #pragma unroll
    for (int i = 0; i < 20; i++) {
        int idx = base + i;
        if (idx < Nn) {
            g_off[idx] = run;
            g_cur[idx] = run;
            run += g_cnt[idx];
        }
    }
}

__global__ void scatter_kernel(const int* __restrict__ edst,
                               const int* __restrict__ esrc) {
    int i = blockIdx.x * blockDim.x + threadIdx.x;
    if (i < Ee/4) {
        int4 d = ((const int4*)edst)[i];
        int4 s = ((const int4*)esrc)[i];
        int p0 = atomicAdd(&g_cur[d.x], 1); g_srt[p0] = s.x;
        int p1 = atomicAdd(&g_cur[d.y], 1); g_srt[p1] = s.y;
        int p2 = atomicAdd(&g_cur[d.z], 1); g_srt[p2] = s.z;
        int p3 = atomicAdd(&g_cur[d.w], 1); g_srt[p3] = s.w;
    }
}

// ---------------- QKVS projection via tensor cores (mma.sync m16n8k16) -----
// C[80000x256] = X[80000x68->80] @ W[80x256], fp16 in, fp32 accum.
// Warp w handles matrix (w>>1), columns (w&1)*32 + nt*8. B fragments
// (weights) preloaded into registers once; X staged fp16 per 32-node chunk.
__global__ void __launch_bounds__(256) qkv_kernel(
    const float* __restrict__ inputs, const float* __restrict__ state,
    const float* __restrict__ Wq, const float* __restrict__ bq,
    const float* __restrict__ Wk, const float* __restrict__ bk,
    const float* __restrict__ Wv, const float* __restrict__ bv,
    const float* __restrict__ Ws, const float* __restrict__ bs)
{
    __shared__ __align__(16) __half sA[32*AS];
    int tid = threadIdx.x;
    int w = tid >> 5, lane = tid & 31, g = lane >> 2, tg = lane & 3;
    int mat = w >> 1;
    const float* Wsel = (mat==0)?Wq:(mat==1)?Wk:(mat==2)?Wv:Ws;
    const float* bsel = (mat==0)?bq:(mat==1)?bk:(mat==2)?bv:bs;

    // preload B fragments (k16n8, .col): b0={B[k][n],B[k+1][n]}, b1 k+8
    unsigned bf[20][2];
    float2 bias[4];
    #pragma unroll
    for (int nt = 0; nt < 4; nt++) {
        int n = (w&1)*32 + nt*8 + g;
        #pragma unroll
        for (int ks = 0; ks < 5; ks++) {
            int k0 = ks*16 + tg*2;
            float w00 = (k0   < Ff) ? __ldg(&Wsel[k0*64 + n])     : 0.f;
            float w01 = (k0+1 < Ff) ? __ldg(&Wsel[(k0+1)*64 + n]) : 0.f;
            float w10 = (k0+8 < Ff) ? __ldg(&Wsel[(k0+8)*64 + n]) : 0.f;
            float w11 = (k0+9 < Ff) ? __ldg(&Wsel[(k0+9)*64 + n]) : 0.f;
            __half2 h0 = __floats2half2_rn(w00, w01);
            __half2 h1 = __floats2half2_rn(w10, w11);
            bf[nt*5+ks][0] = *(unsigned*)&h0;
            bf[nt*5+ks][1] = *(unsigned*)&h1;
        }
        int c0 = (w&1)*32 + nt*8 + tg*2;
        bias[nt] = make_float2(__ldg(&bsel[c0]), __ldg(&bsel[c0+1]));
    }

    // zero pad k rows 65..79 once (row 64 = xin rewritten per chunk)
    for (int i = tid; i < 32*15; i += 256) {
        int node = i / 15, fo = 65 + i % 15;
        sA[node*AS + fo] = __float2half_rn(0.f);
    }

    for (int c = blockIdx.x; c < NODES/32; c += gridDim.x) {
        int base = c * 32;
        __syncthreads();
        // stage X (fp32 global -> fp16 smem), coalesced float4 reads
        for (int i = tid; i < 512; i += 256) {
            int node = i >> 4, f4 = i & 15;
            float4 v = ((const float4*)state)[(size_t)(base+node)*16 + f4];
            __half2 h01 = __floats2half2_rn(v.x, v.y);
            __half2 h23 = __floats2half2_rn(v.z, v.w);
            *(__half2*)&sA[node*AS + f4*4]     = h01;
            *(__half2*)&sA[node*AS + f4*4 + 2] = h23;
        }
        if (tid < 32) {
            int node = base + tid;
            sA[tid*AS + 64] = __float2half_rn(inputs[node]);
            g_mask[node] = (__ldg(&state[(size_t)node*Uu + 58]) != 0.f) ? 1 : 0;
        }
        __syncthreads();

        float acc[2][4][4];
        #pragma unroll
        for (int mt = 0; mt < 2; mt++)
            #pragma unroll
            for (int nt = 0; nt < 4; nt++)
                #pragma unroll
                for (int q = 0; q < 4; q++) acc[mt][nt][q] = 0.f;

        #pragma unroll
        for (int mt = 0; mt < 2; mt++) {
            int r1 = mt*16 + g, r2 = r1 + 8;
            #pragma unroll
            for (int ks = 0; ks < 5; ks++) {
                int kb = ks*16 + tg*2;
                unsigned a0 = *(const unsigned*)&sA[r1*AS + kb];
                unsigned a1 = *(const unsigned*)&sA[r2*AS + kb];
                unsigned a2 = *(const unsigned*)&sA[r1*AS + kb + 8];
                unsigned a3 = *(const unsigned*)&sA[r2*AS + kb + 8];
                #pragma unroll
                for (int nt = 0; nt < 4; nt++) {
                    asm volatile(
                        "mma.sync.aligned.m16n8k16.row.col.f32.f16.f16.f32 "
                        "{%0,%1,%2,%3}, {%4,%5,%6,%7}, {%8,%9}, {%0,%1,%2,%3};"
                        : "+f"(acc[mt][nt][0]), "+f"(acc[mt][nt][1]),
                          "+f"(acc[mt][nt][2]), "+f"(acc[mt][nt][3])
                        : "r"(a0), "r"(a1), "r"(a2), "r"(a3),
                          "r"(bf[nt*5+ks][0]), "r"(bf[nt*5+ks][1]));
                }
            }
        }

        // epilogue: c0,c1 = rows g cols tg*2,+1 ; c2,c3 = rows g+8
        #pragma unroll
        for (int mt = 0; mt < 2; mt++) {
            int n1 = base + mt*16 + g, n2 = n1 + 8;
            #pragma unroll
            for (int nt = 0; nt < 4; nt++) {
                int u0 = (w&1)*32 + nt*8 + tg*2;
                float d0 = acc[mt][nt][0] + bias[nt].x;
                float d1 = acc[mt][nt][1] + bias[nt].y;
                float d2 = acc[mt][nt][2] + bias[nt].x;
                float d3 = acc[mt][nt][3] + bias[nt].y;
                if (mat == 3) {
                    *(float2*)&g_s[(size_t)n1*Uu + u0] = make_float2(d0, d1);
                    *(float2*)&g_s[(size_t)n2*Uu + u0] = make_float2(d2, d3);
                } else {
                    if (mat == 0) {
                        d0 *= ATT_SCALE; d1 *= ATT_SCALE;
                        d2 *= ATT_SCALE; d3 *= ATT_SCALE;
                    }
                    __half* dst = (mat==0)?g_qh:(mat==1)?g_kh:g_vh;
                    __half2 h0 = __floats2half2_rn(d0, d1);
                    __half2 h1 = __floats2half2_rn(d2, d3);
                    *(__half2*)&dst[(size_t)n1*Uu + u0] = h0;
                    *(__half2*)&dst[(size_t)n2*Uu + u0] = h1;
                }
            }
        }
    }
}

// ---------------- attention: one warp per (b, dst), 8 lanes per edge -------
__device__ __forceinline__ void ld_h8(const __half* p, float2 f[4]) {
    uint4 r = *reinterpret_cast<const uint4*>(p);
    f[0] = __half22float2(*reinterpret_cast<__half2*>(&r.x));
    f[1] = __half22float2(*reinterpret_cast<__half2*>(&r.y));
    f[2] = __half22float2(*reinterpret_cast<__half2*>(&r.z));
    f[3] = __half22float2(*reinterpret_cast<__half2*>(&r.w));
}

__global__ void __launch_bounds__(256) attn_kernel() {
    int gw = (blockIdx.x * blockDim.x + threadIdx.x) >> 5;
    if (gw >= NODES) return;
    if (!g_mask[gw]) return;

    int lane = threadIdx.x & 31;
    int grp  = lane >> 3;     // edge slot 0..3
    int sub  = lane & 7;      // dim group: dims [sub*8, sub*8+8)
    int b = gw / Nn;
    int n = gw - b * Nn;

    size_t rowbase = (size_t)gw * Uu;
    float2 q[4];
    ld_h8(g_qh + rowbase + sub*8, q);

    int off = g_off[n];
    int deg = g_cnt[n];
    int end = off + deg;
    const __half* kb = g_kh + (size_t)b * Nn * Uu;
    const __half* vb = g_vh + (size_t)b * Nn * Uu;
    const unsigned char* mk = g_mask + b * Nn;

    float2 acc[4] = {{0,0},{0,0},{0,0},{0,0}};
    float den = 0.f;

    // prefetch first src ids
    int sA_ = 0, sB_ = 0; bool vA = false, vB = false;
    if (off < end) {
        int eA = off + grp, eB = off + 4 + grp;
        vA = eA < end; vB = eB < end;
        sA_ = __ldg(&g_srt[vA ? eA : off]);
        sB_ = __ldg(&g_srt[vB ? eB : off]);
    }

    for (int t = off; t < end; t += 8) {
        int s0 = sA_, s1 = sB_;
        bool val0 = vA, val1 = vB;
        int tn = t + 8;
        if (tn < end) {          // prefetch next iteration's src ids
            int eA = tn + grp, eB = tn + 4 + grp;
            vA = eA < end; vB = eB < end;
            sA_ = __ldg(&g_srt[vA ? eA : off]);
            sB_ = __ldg(&g_srt[vB ? eB : off]);
        }

        // issue all loads up-front (mask, k, v)
        unsigned m0 = mk[s0], m1 = mk[s1];
        float2 k0[4], k1[4], v0[4], v1[4];
        ld_h8(kb + (size_t)s0 * Uu + sub*8, k0);
        ld_h8(kb + (size_t)s1 * Uu + sub*8, k1);
        ld_h8(vb + (size_t)s0 * Uu + sub*8, v0);
        ld_h8(vb + (size_t)s1 * Uu + sub*8, v1);

        float p0 = k0[0].x*q[0].x + k0[0].y*q[0].y
                 + k0[1].x*q[1].x + k0[1].y*q[1].y
                 + k0[2].x*q[2].x + k0[2].y*q[2].y
                 + k0[3].x*q[3].x + k0[3].y*q[3].y;
        float p1 = k1[0].x*q[0].x + k1[0].y*q[0].y
                 + k1[1].x*q[1].x + k1[1].y*q[1].y
                 + k1[2].x*q[2].x + k1[2].y*q[2].y
                 + k1[3].x*q[3].x + k1[3].y*q[3].y;
        #pragma unroll
        for (int d = 1; d < 8; d <<= 1) {
            p0 += __shfl_xor_sync(0xffffffffu, p0, d);
            p1 += __shfl_xor_sync(0xffffffffu, p1, d);
        }
        float w0 = (val0 && m0) ? __expf(p0) : 0.f;
        float w1 = (val1 && m1) ? __expf(p1) : 0.f;

        #pragma unroll
        for (int i = 0; i < 4; i++) {
            acc[i].x += w0 * v0[i].x + w1 * v1[i].x;
            acc[i].y += w0 * v0[i].y + w1 * v1[i].y;
        }
        den += w0 + w1;
    }

    // cross-group reduce (groups 0..3 hold disjoint edge subsets)
    #pragma unroll
    for (int d = 8; d < 32; d <<= 1) {
        #pragma unroll
        for (int i = 0; i < 4; i++) {
            acc[i].x += __shfl_xor_sync(0xffffffffu, acc[i].x, d);
            acc[i].y += __shfl_xor_sync(0xffffffffu, acc[i].y, d);
        }
        den += __shfl_xor_sync(0xffffffffu, den, d);
    }

    if (lane < 8) {
        float inv = (den > 0.f) ? 1.f / fmaxf(den, 1e-16f) : 0.f;
        const float4* sp = (const float4*)(g_s + rowbase + sub * 8);
        float4 s0 = sp[0], s1 = sp[1];
        float4* op = (float4*)(g_agg + rowbase + sub * 8);
        op[0] = make_float4(acc[0].x*inv + s0.x, acc[0].y*inv + s0.y,
                            acc[1].x*inv + s0.z, acc[1].y*inv + s0.w);
        op[1] = make_float4(acc[2].x*inv + s1.x, acc[2].y*inv + s1.y,
                            acc[3].x*inv + s1.z, acc[3].y*inv + s1.w);
    }
}

// ---------------- slim GRU: gates + output (h2 precomputed) ----------------
__global__ void __launch_bounds__(256, 4) gru_kernel(
    const float* __restrict__ inputs, const float* __restrict__ state,
    const float* __restrict__ W1, const float* __restrict__ b1,
    const float* __restrict__ W2, const float* __restrict__ b2,
    float* __restrict__ out)
{
    extern __shared__ float sm[];
    __half* sW1ah = (__half*)sm;             // cols 0..63 (reset)
    __half* sW1bh = sW1ah + 64*FPH;          // cols 64..127 (z)
    __half* sW2h  = sW1bh + 64*FPH;
    float* sb1 = (float*)(sW2h + 64*FPH);    // 128
    float* sb2 = sb1 + 128;                  // 64
    float* sh2T = sb2 + 64;                  // 68*XS

    for (int i = threadIdx.x; i < Ff*128; i += 256) {
        int f = i >> 7, c = i & 127;
        int fp = (f == 0) ? 64 : (f - 1);    // permute: xin -> row 64
        if (c < 64) sW1ah[c*FPH + fp] = __float2half_rn(W1[i]);
        else        sW1bh[(c-64)*FPH + fp] = __float2half_rn(W1[i]);
    }
    for (int i = threadIdx.x; i < Ff*Uu; i += 256) {
        int f = i >> 6, u = i & 63;
        int fp = (f == 0) ? 64 : (f - 1);
        sW2h[u*FPH + fp] = __float2half_rn(W2[i]);
    }
    for (int i = threadIdx.x; i < 192; i += 256) {
        int u = i & 63, p = i >> 6;
        sW1ah[u*FPH + 65 + p] = __float2half_rn(0.f);
        sW1bh[u*FPH + 65 + p] = __float2half_rn(0.f);
        sW2h[u*FPH + 65 + p]  = __float2half_rn(0.f);
    }
    if (threadIdx.x < 128) sb1[threadIdx.x] = b1[threadIdx.x];
    if (threadIdx.x < 64)  sb2[threadIdx.x] = b2[threadIdx.x];
    if (threadIdx.x < 96) {              // zero pad rows 65..67 once
        int r = 65 + threadIdx.x / 32;
        sh2T[r*XS + (threadIdx.x & 31)] = 0.f;
    }
    __syncthreads();

    int u = threadIdx.x & 63;
    int g = threadIdx.x >> 6;
    int ln0 = g * 8;
    const uint2* w1a2 = (const uint2*)(sW1ah + u*FPH);
    const uint2* w1b2 = (const uint2*)(sW1bh + u*FPH);
    const uint2* w22  = (const uint2*)(sW2h  + u*FPH);
    int uswz = 4*((u >> 2) & 7);         // swizzle for row u

    for (int c = blockIdx.x; c < NODES/32; c += gridDim.x) {
        int base = c * 32;
        __syncthreads();
        // stage h2 rows 0..63 (select agg vs state by mask), xin row 64
        #pragma unroll
        for (int i = threadIdx.x; i < 512; i += 256) {
            int node = i >> 4, f4 = i & 15;
            bool msk = g_mask[base + node];
            float4 v = msk
                ? ((const float4*)g_agg)[(size_t)(base + node)*16 + f4]
                : ((const float4*)state)[(size_t)(base + node)*16 + f4];
            int np = node ^ (4*(f4 & 7));
            sh2T[(f4*4+0)*XS + np] = v.x;
            sh2T[(f4*4+1)*XS + np] = v.y;
            sh2T[(f4*4+2)*XS + np] = v.z;
            sh2T[(f4*4+3)*XS + np] = v.w;
        }
        if (threadIdx.x < 32) {
            sh2T[64*XS + threadIdx.x] = inputs[base + threadIdx.x];
        }
        __syncthreads();

        float h2v[8];
        #pragma unroll
        for (int j = 0; j < 8; j++)
            h2v[j] = sh2T[u*XS + ((ln0 + j) ^ uswz)];

        // gates: a1 (reset), a2 (z) = [h2, xin] @ W1' + b1
        ull a1[4], a2[4];
        ull b1a = pack2(sb1[u]), b1b = pack2(sb1[64+u]);
        #pragma unroll
        for (int p = 0; p < 4; p++) { a1[p] = b1a; a2[p] = b1b; }
        #pragma unroll 4
        for (int f4 = 0; f4 < 17; f4++) {
            uint2 ra = w1a2[f4], rb = w1b2[f4];
            float2 a01 = __half22float2(*(const __half2*)&ra.x);
            float2 a23 = __half22float2(*(const __half2*)&ra.y);
            float2 b01 = __half22float2(*(const __half2*)&rb.x);
            float2 b23 = __half22float2(*(const __half2*)&rb.y);
            int off = ln0 ^ (4*(f4 & 7));     // f4=16 -> 0 (xin/pad rows plain)
            #pragma unroll
            for (int e = 0; e < 4; e++) {
                int f = f4*4 + e;
                ulonglong2 xab = *(const ulonglong2*)(sh2T + f*XS + off);
                ulonglong2 xcd = *(const ulonglong2*)(sh2T + f*XS + (off^4));
                float wae = (e==0)?a01.x:(e==1)?a01.y:(e==2)?a23.x:a23.y;
                float wbe = (e==0)?b01.x:(e==1)?b01.y:(e==2)?b23.x:b23.y;
                ull wa2 = pack2(wae), wb2 = pack2(wbe);
                fma2(a1[0], xab.x, wa2); fma2(a1[1], xab.y, wa2);
                fma2(a1[2], xcd.x, wa2); fma2(a1[3], xcd.y, wa2);
                fma2(a2[0], xab.x, wb2); fma2(a2[1], xab.y, wb2);
                fma2(a2[2], xcd.x, wb2); fma2(a2[3], xcd.y, wb2);
            }
        }
        float zz[8], rst[8];
        #pragma unroll
        for (int p = 0; p < 4; p++) {
            float2 f1 = unpack2(a1[p]);
            float2 f2 = unpack2(a2[p]);
            rst[2*p]   = 1.f / (1.f + __expf(-f1.x));
            rst[2*p+1] = 1.f / (1.f + __expf(-f1.y));
            zz[2*p]    = 1.f / (1.f + __expf(-f2.x));
            zz[2*p+1]  = 1.f / (1.f + __expf(-f2.y));
        }
        __syncthreads();     // all gate reads of sh2T complete

        // overwrite row u in place with reset*h2 (row 64 = xin unchanged)
        #pragma unroll
        for (int j = 0; j < 8; j++)
            sh2T[u*XS + ((ln0 + j) ^ uswz)] = rst[j] * h2v[j];
        __syncthreads();

        // c = tanh([reset*h2, xin] @ W2' + b2); out = (1-z) h2 + z c
        ull cacc[4];
        ull b2p = pack2(sb2[u]);
        #pragma unroll
        for (int p = 0; p < 4; p++) cacc[p] = b2p;
        #pragma unroll 4
        for (int f4 = 0; f4 < 17; f4++) {
            uint2 rw = w22[f4];
            float2 w01 = __half22float2(*(const __half2*)&rw.x);
            float2 w23 = __half22float2(*(const __half2*)&rw.y);
            int off = ln0 ^ (4*(f4 & 7));
            #pragma unroll
            for (int e = 0; e < 4; e++) {
                int f = f4*4 + e;
                ulonglong2 xab = *(const ulonglong2*)(sh2T + f*XS + off);
                ulonglong2 xcd = *(const ulonglong2*)(sh2T + f*XS + (off^4));
                float we = (e==0)?w01.x:(e==1)?w01.y:(e==2)?w23.x:w23.y;
                ull w2_ = pack2(we);
                fma2(cacc[0], xab.x, w2_); fma2(cacc[1], xab.y, w2_);
                fma2(cacc[2], xcd.x, w2_); fma2(cacc[3], xcd.y, w2_);
            }
        }
        #pragma unroll
        for (int p = 0; p < 4; p++) {
            float2 f2 = unpack2(cacc[p]);
            int j0 = 2*p;
            float cc0 = tanhf(f2.x), cc1 = tanhf(f2.y);
            size_t i0 = (size_t)(base + ln0 + j0)*Uu + u;
            out[i0]      = (1.f - zz[j0])   * h2v[j0]   + zz[j0]   * cc0;
            out[i0 + Uu] = (1.f - zz[j0+1]) * h2v[j0+1] + zz[j0+1] * cc1;
        }
    }
}

// ---------------- launch (fork CSR chain parallel to qkv) ------------------
static cudaStream_t g_s2 = nullptr;
static cudaEvent_t  g_evFork = nullptr, g_evJoin = nullptr;

extern "C" void kernel_launch(void* const* d_in, const int* in_sizes, int n_in,
                              void* d_out, int out_size)
{
    const float* inputs = (const float*)d_in[0];
    const float* state  = (const float*)d_in[1];
    const int*   esrc   = (const int*)d_in[2];
    const int*   edst   = (const int*)d_in[3];
    const float* Wq = (const float*)d_in[4];
    const float* bq = (const float*)d_in[5];
    const float* Wk = (const float*)d_in[6];
    const float* bk = (const float*)d_in[7];
    const float* Wv = (const float*)d_in[8];
    const float* bv = (const float*)d_in[9];
    const float* Ws = (const float*)d_in[10];
    const float* bs = (const float*)d_in[11];
    const float* W1 = (const float*)d_in[12];
    const float* b1 = (const float*)d_in[13];
    const float* W2 = (const float*)d_in[14];
    const float* b2 = (const float*)d_in[15];
    float* out = (float*)d_out;

    const int SMEM_D = 3*64*FPH*2 + 192*4 + 68*XS*4;            // 36672

    if (g_s2 == nullptr) {
        cudaStreamCreateWithFlags(&g_s2, cudaStreamNonBlocking);
        cudaEventCreateWithFlags(&g_evFork, cudaEventDisableTiming);
        cudaEventCreateWithFlags(&g_evJoin, cudaEventDisableTiming);
        cudaFuncSetAttribute(gru_kernel, cudaFuncAttributeMaxDynamicSharedMemorySize, SMEM_D);
    }

    void* cnt_ptr = nullptr;
    cudaGetSymbolAddress(&cnt_ptr, g_cnt);

    // fork: CSR build chain on side stream, projections on main stream
    cudaEventRecord(g_evFork, 0);
    cudaStreamWaitEvent(g_s2, g_evFork, 0);

    cudaMemsetAsync(cnt_ptr, 0, Nn * sizeof(int), g_s2);
    hist_kernel<<<(Ee/4 + 255)/256, 256, 0, g_s2>>>(edst);
    scan_kernel<<<1, 1024, 0, g_s2>>>();
    scatter_kernel<<<(Ee/4 + 255)/256, 256, 0, g_s2>>>(edst, esrc);

    // tensor-core QKVS projection
    qkv_kernel<<<592, 256>>>(inputs, state, Wq, bq, Wk, bk, Wv, bv, Ws, bs);

    // join
    cudaEventRecord(g_evJoin, g_s2);
    cudaStreamWaitEvent(0, g_evJoin, 0);

    // attention: one warp per (b, dst); writes h2 for masked nodes
    attn_kernel<<<(NODES*32 + 255)/256, 256>>>();

    // slim GRU (4 CTAs/SM)
    gru_kernel<<<444, 256, SMEM_D>>>(inputs, state, W1, b1, W2, b2, out);
}

// round 16
// speedup vs baseline: 1.4661x; 1.4661x over previous
#include <cuda_runtime.h>
#include <cuda_fp16.h>
#include <math.h>

#define Bb 4
#define Nn 20000
#define Uu 64
#define Ff 65
#define Ee 640000
#define NODES (Bb*Nn)
#define ATT_SCALE 0.125f
#define FPH 68         // padded weight row stride (halves)
#define XS 36          // f-major x row stride (floats), mult of 4

typedef unsigned long long ull;

__device__ __forceinline__ ull pack2(float v) {
    ull r; asm("mov.b64 %0, {%1, %1};" : "=l"(r) : "f"(v)); return r;
}
__device__ __forceinline__ void fma2(ull &acc, ull x, ull w) {
    asm("fma.rn.f32x2 %0, %1, %2, %0;" : "+l"(acc) : "l"(x), "l"(w));
}
__device__ __forceinline__ float2 unpack2(ull v) {
    float2 f; asm("mov.b64 {%0, %1}, %2;" : "=f"(f.x), "=f"(f.y) : "l"(v)); return f;
}

// ---------------- device scratch (static, no runtime alloc) ----------------
__device__ __align__(16) __half g_qh[NODES*Uu];    // prescaled by ATT_SCALE
__device__ __align__(16) __half g_kvh[NODES*128];  // fused: k cols 0..63, v cols 64..127
__device__ __align__(16) float  g_s[NODES*Uu];     // x@Ws + bs (fp32)
__device__ __align__(16) float  g_agg[NODES*Uu];   // h2 for masked nodes
__device__ unsigned char g_mask[NODES];
__device__ int g_cnt[Nn];
__device__ int g_off[Nn];
__device__ int g_cur[Nn];
__device__ int g_srt[Ee];   // src ids sorted by dst (CSR payload)

// ---------------- CSR build ----------------
__global__ void hist_kernel(const int* __restrict__ edst) {
    int i = blockIdx.x * blockDim.x + threadIdx.x;
    if (i < Ee/4) {
        int4 d = ((const int4*)edst)[i];
        atomicAdd(&g_cnt[d.x], 1);
        atomicAdd(&g_cnt[d.y], 1);
        atomicAdd(&g_cnt[d.z], 1);
        atomicAdd(&g_cnt[d.w], 1);
    }
}

__global__ void scan_kernel() {
    __shared__ int sp[1024];
    int tid = threadIdx.x;
    int base = tid * 20;
    int s = 0;
    #pragma unroll
    for (int i = 0; i < 20; i++) {
        int idx = base + i;
        if (idx < Nn) s += g_cnt[idx];
    }
    sp[tid] = s;
    __syncthreads();
    for (int d = 1; d < 1024; d <<= 1) {
        int v = (tid >= d) ? sp[tid - d] : 0;
        __syncthreads();
        sp[tid] += v;
        __syncthreads();
    }
    int run = sp[tid] - s;   // exclusive prefix
    #pragma unroll
    for (int i = 0; i < 20; i++) {
        int idx = base + i;
        if (idx < Nn) {
            g_off[idx] = run;
            g_cur[idx] = run;
            run += g_cnt[idx];
        }
    }
}

__global__ void scatter_kernel(const int* __restrict__ edst,
                               const int* __restrict__ esrc) {
    int i = blockIdx.x * blockDim.x + threadIdx.x;
    if (i < Ee/4) {
        int4 d = ((const int4*)edst)[i];
        int4 s = ((const int4*)esrc)[i];
        int p0 = atomicAdd(&g_cur[d.x], 1); g_srt[p0] = s.x;
        int p1 = atomicAdd(&g_cur[d.y], 1); g_srt[p1] = s.y;
        int p2 = atomicAdd(&g_cur[d.z], 1); g_srt[p2] = s.z;
        int p3 = atomicAdd(&g_cur[d.w], 1); g_srt[p3] = s.w;
    }
}

// ---------------- QKVS projection + mask (fp16 weights, f32x2 math) --------
__global__ void __launch_bounds__(256, 3) qkv_kernel(
    const float* __restrict__ inputs, const float* __restrict__ state,
    const float* __restrict__ Wq, const float* __restrict__ bq,
    const float* __restrict__ Wk, const float* __restrict__ bk,
    const float* __restrict__ Wv, const float* __restrict__ bv,
    const float* __restrict__ Ws, const float* __restrict__ bs)
{
    extern __shared__ float sm[];
    __half* sWqh = (__half*)sm;               // 64*FPH halves each
    __half* sWkh = sWqh + 64*FPH;
    __half* sWvh = sWkh + 64*FPH;
    __half* sWsh = sWvh + 64*FPH;
    float* sb  = (float*)(sWsh + 64*FPH);     // 256
    float* sxT = sb + 256;                    // 68*XS (swizzled)

    for (int i = threadIdx.x; i < Ff*Uu; i += 256) {
        int f = i >> 6, u = i & 63;
        sWqh[u*FPH + f] = __float2half_rn(Wq[i]);
        sWkh[u*FPH + f] = __float2half_rn(Wk[i]);
        sWvh[u*FPH + f] = __float2half_rn(Wv[i]);
        sWsh[u*FPH + f] = __float2half_rn(Ws[i]);
    }
    for (int i = threadIdx.x; i < 192; i += 256) {
        int u = i & 63, p = i >> 6;    // pad f=65..67
        sWqh[u*FPH + 65 + p] = __float2half_rn(0.f);
        sWkh[u*FPH + 65 + p] = __float2half_rn(0.f);
        sWvh[u*FPH + 65 + p] = __float2half_rn(0.f);
        sWsh[u*FPH + 65 + p] = __float2half_rn(0.f);
    }
    if (threadIdx.x < 256) sb[threadIdx.x] =
        (threadIdx.x < 64)  ? bq[threadIdx.x] :
        (threadIdx.x < 128) ? bk[threadIdx.x - 64] :
        (threadIdx.x < 192) ? bv[threadIdx.x - 128] : bs[threadIdx.x - 192];
    if (threadIdx.x < 96) {            // zero pad rows 65..67 once
        int r = 65 + threadIdx.x / 32;
        sxT[r*XS + (threadIdx.x & 31)] = 0.f;
    }
    __syncthreads();

    int u = threadIdx.x & 63;
    int g = threadIdx.x >> 6;
    int ln0 = g * 8;
    const uint2* wq2 = (const uint2*)(sWqh + u*FPH);
    const uint2* wk2 = (const uint2*)(sWkh + u*FPH);
    const uint2* wv2 = (const uint2*)(sWvh + u*FPH);
    const uint2* ws2 = (const uint2*)(sWsh + u*FPH);

    for (int c = blockIdx.x; c < NODES/32; c += gridDim.x) {
        int base = c * 32;
        __syncthreads();
        // coalesced float4 reads; swizzled transposed writes
        #pragma unroll
        for (int i = threadIdx.x; i < 512; i += 256) {
            int node = i >> 4, f4 = i & 15;
            float4 v = ((const float4*)state)[(size_t)(base + node)*16 + f4];
            int np = node ^ (4*(f4 & 7));
            sxT[(f4*4+0)*XS + np] = v.x;
            sxT[(f4*4+1)*XS + np] = v.y;
            sxT[(f4*4+2)*XS + np] = v.z;
            sxT[(f4*4+3)*XS + np] = v.w;
        }
        if (threadIdx.x < 32) {
            int node = base + threadIdx.x;
            sxT[64*XS + threadIdx.x] = inputs[node];   // f4=16 -> s=0
            g_mask[node] = (__ldg(&state[(size_t)node*Uu + 58]) != 0.f) ? 1 : 0;
        }
        __syncthreads();

        ull aq[4], ak[4], av[4], as_[4];
        #pragma unroll
        for (int p = 0; p < 4; p++) { aq[p]=0ull; ak[p]=0ull; av[p]=0ull; as_[p]=0ull; }

        #pragma unroll 4
        for (int f4 = 0; f4 < 17; f4++) {
            uint2 rq = wq2[f4], rk = wk2[f4], rv = wv2[f4], rs = ws2[f4];
            float2 q01 = __half22float2(*(const __half2*)&rq.x);
            float2 q23 = __half22float2(*(const __half2*)&rq.y);
            float2 k01 = __half22float2(*(const __half2*)&rk.x);
            float2 k23 = __half22float2(*(const __half2*)&rk.y);
            float2 v01 = __half22float2(*(const __half2*)&rv.x);
            float2 v23 = __half22float2(*(const __half2*)&rv.y);
            float2 s01 = __half22float2(*(const __half2*)&rs.x);
            float2 s23 = __half22float2(*(const __half2*)&rs.y);
            int off = ln0 ^ (4*(f4 & 7));     // f4=16 -> 0
            #pragma unroll
            for (int e = 0; e < 4; e++) {
                int f = f4*4 + e;
                ulonglong2 xab = *(const ulonglong2*)(sxT + f*XS + off);
                ulonglong2 xcd = *(const ulonglong2*)(sxT + f*XS + (off^4));
                float wqe = (e==0)?q01.x:(e==1)?q01.y:(e==2)?q23.x:q23.y;
                float wke = (e==0)?k01.x:(e==1)?k01.y:(e==2)?k23.x:k23.y;
                float wve = (e==0)?v01.x:(e==1)?v01.y:(e==2)?v23.x:v23.y;
                float wse = (e==0)?s01.x:(e==1)?s01.y:(e==2)?s23.x:s23.y;
                ull wq_ = pack2(wqe), wk_ = pack2(wke), wv_ = pack2(wve), ws_ = pack2(wse);
                fma2(aq[0], xab.x, wq_); fma2(aq[1], xab.y, wq_);
                fma2(aq[2], xcd.x, wq_); fma2(aq[3], xcd.y, wq_);
                fma2(ak[0], xab.x, wk_); fma2(ak[1], xab.y, wk_);
                fma2(ak[2], xcd.x, wk_); fma2(ak[3], xcd.y, wk_);
                fma2(av[0], xab.x, wv_); fma2(av[1], xab.y, wv_);
                fma2(av[2], xcd.x, wv_); fma2(av[3], xcd.y, wv_);
                fma2(as_[0], xab.x, ws_); fma2(as_[1], xab.y, ws_);
                fma2(as_[2], xcd.x, ws_); fma2(as_[3], xcd.y, ws_);
            }
        }
        float bqv = sb[u], bkv = sb[64+u], bvv = sb[128+u], bsv = sb[192+u];
        #pragma unroll
        for (int p = 0; p < 4; p++) {
            float2 fq = unpack2(aq[p]);
            float2 fk = unpack2(ak[p]);
            float2 fv = unpack2(av[p]);
            float2 fs = unpack2(as_[p]);
            size_t nq = (size_t)(base + ln0 + 2*p);
            size_t i0 = nq*Uu + u;
            size_t kv0 = nq*128 + u;
            g_qh[i0]       = __float2half_rn((fq.x + bqv) * ATT_SCALE);
            g_qh[i0 + Uu]  = __float2half_rn((fq.y + bqv) * ATT_SCALE);
            g_kvh[kv0]           = __float2half_rn(fk.x + bkv);
            g_kvh[kv0 + 128]     = __float2half_rn(fk.y + bkv);
            g_kvh[kv0 + 64]      = __float2half_rn(fv.x + bvv);
            g_kvh[kv0 + 64 + 128]= __float2half_rn(fv.y + bvv);
            g_s[i0]        = fs.x + bsv;
            g_s[i0 + Uu]   = fs.y + bsv;
        }
    }
}

// ---------------- attention: one warp per (b, dst), 8 lanes per edge -------
__device__ __forceinline__ void ld_h8(const __half* p, float2 f[4]) {
    uint4 r = *reinterpret_cast<const uint4*>(p);
    f[0] = __half22float2(*reinterpret_cast<__half2*>(&r.x));
    f[1] = __half22float2(*reinterpret_cast<__half2*>(&r.y));
    f[2] = __half22float2(*reinterpret_cast<__half2*>(&r.z));
    f[3] = __half22float2(*reinterpret_cast<__half2*>(&r.w));
}

__global__ void __launch_bounds__(256) attn_kernel() {
    int gw = (blockIdx.x * blockDim.x + threadIdx.x) >> 5;
    if (gw >= NODES) return;
    if (!g_mask[gw]) return;

    int lane = threadIdx.x & 31;
    int grp  = lane >> 3;     // edge slot 0..3
    int sub  = lane & 7;      // dim group: dims [sub*8, sub*8+8)
    int b = gw / Nn;
    int n = gw - b * Nn;

    size_t rowbase = (size_t)gw * Uu;
    float2 q[4];
    ld_h8(g_qh + rowbase + sub*8, q);

    int off = g_off[n];
    int deg = g_cnt[n];
    int end = off + deg;
    const __half* kvb = g_kvh + (size_t)b * Nn * 128;
    const unsigned char* mk = g_mask + b * Nn;

    float2 acc[4] = {{0,0},{0,0},{0,0},{0,0}};
    float den = 0.f;

    // prefetch first src ids
    int sA = 0, sB = 0; bool vA = false, vB = false;
    if (off < end) {
        int eA = off + grp, eB = off + 4 + grp;
        vA = eA < end; vB = eB < end;
        sA = __ldg(&g_srt[vA ? eA : off]);
        sB = __ldg(&g_srt[vB ? eB : off]);
    }

    for (int t = off; t < end; t += 8) {
        int s0 = sA, s1 = sB;
        bool val0 = vA, val1 = vB;
        int tn = t + 8;
        if (tn < end) {          // prefetch next iteration's src ids
            int eA = tn + grp, eB = tn + 4 + grp;
            vA = eA < end; vB = eB < end;
            sA = __ldg(&g_srt[vA ? eA : off]);
            sB = __ldg(&g_srt[vB ? eB : off]);
        }

        // issue all loads up-front (mask, k+v fused rows)
        unsigned m0 = mk[s0], m1 = mk[s1];
        const __half* r0 = kvb + (size_t)s0 * 128 + sub*8;
        const __half* r1 = kvb + (size_t)s1 * 128 + sub*8;
        float2 k0[4], k1[4], v0[4], v1[4];
        ld_h8(r0, k0);
        ld_h8(r1, k1);
        ld_h8(r0 + 64, v0);
        ld_h8(r1 + 64, v1);

        float p0 = k0[0].x*q[0].x + k0[0].y*q[0].y
                 + k0[1].x*q[1].x + k0[1].y*q[1].y
                 + k0[2].x*q[2].x + k0[2].y*q[2].y
                 + k0[3].x*q[3].x + k0[3].y*q[3].y;
        float p1 = k1[0].x*q[0].x + k1[0].y*q[0].y
                 + k1[1].x*q[1].x + k1[1].y*q[1].y
                 + k1[2].x*q[2].x + k1[2].y*q[2].y
                 + k1[3].x*q[3].x + k1[3].y*q[3].y;
        #pragma unroll
        for (int d = 1; d < 8; d <<= 1) {
            p0 += __shfl_xor_sync(0xffffffffu, p0, d);
            p1 += __shfl_xor_sync(0xffffffffu, p1, d);
        }
        float w0 = (val0 && m0) ? __expf(p0) : 0.f;
        float w1 = (val1 && m1) ? __expf(p1) : 0.f;

        #pragma unroll
        for (int i = 0; i < 4; i++) {
            acc[i].x += w0 * v0[i].x + w1 * v1[i].x;
            acc[i].y += w0 * v0[i].y + w1 * v1[i].y;
        }
        den += w0 + w1;
    }

    // cross-group reduce (groups 0..3 hold disjoint edge subsets)
    #pragma unroll
    for (int d = 8; d < 32; d <<= 1) {
        #pragma unroll
        for (int i = 0; i < 4; i++) {
            acc[i].x += __shfl_xor_sync(0xffffffffu, acc[i].x, d);
            acc[i].y += __shfl_xor_sync(0xffffffffu, acc[i].y, d);
        }
        den += __shfl_xor_sync(0xffffffffu, den, d);
    }

    if (lane < 8) {
        float inv = (den > 0.f) ? 1.f / fmaxf(den, 1e-16f) : 0.f;
        const float4* sp = (const float4*)(g_s + rowbase + sub * 8);
        float4 s0 = sp[0], s1 = sp[1];
        float4* op = (float4*)(g_agg + rowbase + sub * 8);
        op[0] = make_float4(acc[0].x*inv + s0.x, acc[0].y*inv + s0.y,
                            acc[1].x*inv + s0.z, acc[1].y*inv + s0.w);
        op[1] = make_float4(acc[2].x*inv + s1.x, acc[2].y*inv + s1.y,
                            acc[3].x*inv + s1.z, acc[3].y*inv + s1.w);
    }
}

// ---------------- slim GRU: gates + output (h2 precomputed) ----------------
__global__ void __launch_bounds__(256, 4) gru_kernel(
    const float* __restrict__ inputs, const float* __restrict__ state,
    const float* __restrict__ W1, const float* __restrict__ b1,
    const float* __restrict__ W2, const float* __restrict__ b2,
    float* __restrict__ out)
{
    extern __shared__ float sm[];
    __half* sW1ah = (__half*)sm;             // cols 0..63 (reset)
    __half* sW1bh = sW1ah + 64*FPH;          // cols 64..127 (z)
    __half* sW2h  = sW1bh + 64*FPH;
    float* sb1 = (float*)(sW2h + 64*FPH);    // 128
    float* sb2 = sb1 + 128;                  // 64
    float* sh2T = sb2 + 64;                  // 68*XS

    for (int i = threadIdx.x; i < Ff*128; i += 256) {
        int f = i >> 7, c = i & 127;
        int fp = (f == 0) ? 64 : (f - 1);    // permute: xin -> row 64
        if (c < 64) sW1ah[c*FPH + fp] = __float2half_rn(W1[i]);
        else        sW1bh[(c-64)*FPH + fp] = __float2half_rn(W1[i]);
    }
    for (int i = threadIdx.x; i < Ff*Uu; i += 256) {
        int f = i >> 6, u = i & 63;
        int fp = (f == 0) ? 64 : (f - 1);
        sW2h[u*FPH + fp] = __float2half_rn(W2[i]);
    }
    for (int i = threadIdx.x; i < 192; i += 256) {
        int u = i & 63, p = i >> 6;
        sW1ah[u*FPH + 65 + p] = __float2half_rn(0.f);
        sW1bh[u*FPH + 65 + p] = __float2half_rn(0.f);
        sW2h[u*FPH + 65 + p]  = __float2half_rn(0.f);
    }
    if (threadIdx.x < 128) sb1[threadIdx.x] = b1[threadIdx.x];
    if (threadIdx.x < 64)  sb2[threadIdx.x] = b2[threadIdx.x];
    if (threadIdx.x < 96) {              // zero pad rows 65..67 once
        int r = 65 + threadIdx.x / 32;
        sh2T[r*XS + (threadIdx.x & 31)] = 0.f;
    }
    __syncthreads();

    int u = threadIdx.x & 63;
    int g = threadIdx.x >> 6;
    int ln0 = g * 8;
    const uint2* w1a2 = (const uint2*)(sW1ah + u*FPH);
    const uint2* w1b2 = (const uint2*)(sW1bh + u*FPH);
    const uint2* w22  = (const uint2*)(sW2h  + u*FPH);
    int uswz = 4*((u >> 2) & 7);         // swizzle for row u

    for (int c = blockIdx.x; c < NODES/32; c += gridDim.x) {
        int base = c * 32;
        __syncthreads();
        // stage h2 rows 0..63 (select agg vs state by mask), xin row 64
        #pragma unroll
        for (int i = threadIdx.x; i < 512; i += 256) {
            int node = i >> 4, f4 = i & 15;
            bool msk = g_mask[base + node];
            float4 v = msk
                ? ((const float4*)g_agg)[(size_t)(base + node)*16 + f4]
                : ((const float4*)state)[(size_t)(base + node)*16 + f4];
            int np = node ^ (4*(f4 & 7));
            sh2T[(f4*4+0)*XS + np] = v.x;
            sh2T[(f4*4+1)*XS + np] = v.y;
            sh2T[(f4*4+2)*XS + np] = v.z;
            sh2T[(f4*4+3)*XS + np] = v.w;
        }
        if (threadIdx.x < 32) {
            sh2T[64*XS + threadIdx.x] = inputs[base + threadIdx.x];
        }
        __syncthreads();

        float h2v[8];
        #pragma unroll
        for (int j = 0; j < 8; j++)
            h2v[j] = sh2T[u*XS + ((ln0 + j) ^ uswz)];

        // gates: a1 (reset), a2 (z) = [h2, xin] @ W1' + b1
        ull a1[4], a2[4];
        ull b1a = pack2(sb1[u]), b1b = pack2(sb1[64+u]);
        #pragma unroll
        for (int p = 0; p < 4; p++) { a1[p] = b1a; a2[p] = b1b; }
        #pragma unroll 4
        for (int f4 = 0; f4 < 17; f4++) {
            uint2 ra = w1a2[f4], rb = w1b2[f4];
            float2 a01 = __half22float2(*(const __half2*)&ra.x);
            float2 a23 = __half22float2(*(const __half2*)&ra.y);
            float2 b01 = __half22float2(*(const __half2*)&rb.x);
            float2 b23 = __half22float2(*(const __half2*)&rb.y);
            int off = ln0 ^ (4*(f4 & 7));     // f4=16 -> 0 (xin/pad rows plain)
            #pragma unroll
            for (int e = 0; e < 4; e++) {
                int f = f4*4 + e;
                ulonglong2 xab = *(const ulonglong2*)(sh2T + f*XS + off);
                ulonglong2 xcd = *(const ulonglong2*)(sh2T + f*XS + (off^4));
                float wae = (e==0)?a01.x:(e==1)?a01.y:(e==2)?a23.x:a23.y;
                float wbe = (e==0)?b01.x:(e==1)?b01.y:(e==2)?b23.x:b23.y;
                ull wa2 = pack2(wae), wb2 = pack2(wbe);
                fma2(a1[0], xab.x, wa2); fma2(a1[1], xab.y, wa2);
                fma2(a1[2], xcd.x, wa2); fma2(a1[3], xcd.y, wa2);
                fma2(a2[0], xab.x, wb2); fma2(a2[1], xab.y, wb2);
                fma2(a2[2], xcd.x, wb2); fma2(a2[3], xcd.y, wb2);
            }
        }
        float zz[8], rst[8];
        #pragma unroll
        for (int p = 0; p < 4; p++) {
            float2 f1 = unpack2(a1[p]);
            float2 f2 = unpack2(a2[p]);
            rst[2*p]   = 1.f / (1.f + __expf(-f1.x));
            rst[2*p+1] = 1.f / (1.f + __expf(-f1.y));
            zz[2*p]    = 1.f / (1.f + __expf(-f2.x));
            zz[2*p+1]  = 1.f / (1.f + __expf(-f2.y));
        }
        __syncthreads();     // all gate reads of sh2T complete

        // overwrite row u in place with reset*h2 (row 64 = xin unchanged)
        #pragma unroll
        for (int j = 0; j < 8; j++)
            sh2T[u*XS + ((ln0 + j) ^ uswz)] = rst[j] * h2v[j];
        __syncthreads();

        // c = tanh([reset*h2, xin] @ W2' + b2); out = (1-z) h2 + z c
        ull cacc[4];
        ull b2p = pack2(sb2[u]);
        #pragma unroll
        for (int p = 0; p < 4; p++) cacc[p] = b2p;
        #pragma unroll 4
        for (int f4 = 0; f4 < 17; f4++) {
            uint2 rw = w22[f4];
            float2 w01 = __half22float2(*(const __half2*)&rw.x);
            float2 w23 = __half22float2(*(const __half2*)&rw.y);
            int off = ln0 ^ (4*(f4 & 7));
            #pragma unroll
            for (int e = 0; e < 4; e++) {
                int f = f4*4 + e;
                ulonglong2 xab = *(const ulonglong2*)(sh2T + f*XS + off);
                ulonglong2 xcd = *(const ulonglong2*)(sh2T + f*XS + (off^4));
                float we = (e==0)?w01.x:(e==1)?w01.y:(e==2)?w23.x:w23.y;
                ull w2_ = pack2(we);
                fma2(cacc[0], xab.x, w2_); fma2(cacc[1], xab.y, w2_);
                fma2(cacc[2], xcd.x, w2_); fma2(cacc[3], xcd.y, w2_);
            }
        }
        #pragma unroll
        for (int p = 0; p < 4; p++) {
            float2 f2 = unpack2(cacc[p]);
            int j0 = 2*p;
            float cc0 = tanhf(f2.x), cc1 = tanhf(f2.y);
            size_t i0 = (size_t)(base + ln0 + j0)*Uu + u;
            out[i0]      = (1.f - zz[j0])   * h2v[j0]   + zz[j0]   * cc0;
            out[i0 + Uu] = (1.f - zz[j0+1]) * h2v[j0+1] + zz[j0+1] * cc1;
        }
    }
}

// ---------------- launch (fork CSR chain parallel to qkv) ------------------
static cudaStream_t g_s2 = nullptr;
static cudaEvent_t  g_evFork = nullptr, g_evJoin = nullptr;

extern "C" void kernel_launch(void* const* d_in, const int* in_sizes, int n_in,
                              void* d_out, int out_size)
{
    const float* inputs = (const float*)d_in[0];
    const float* state  = (const float*)d_in[1];
    const int*   esrc   = (const int*)d_in[2];
    const int*   edst   = (const int*)d_in[3];
    const float* Wq = (const float*)d_in[4];
    const float* bq = (const float*)d_in[5];
    const float* Wk = (const float*)d_in[6];
    const float* bk = (const float*)d_in[7];
    const float* Wv = (const float*)d_in[8];
    const float* bv = (const float*)d_in[9];
    const float* Ws = (const float*)d_in[10];
    const float* bs = (const float*)d_in[11];
    const float* W1 = (const float*)d_in[12];
    const float* b1 = (const float*)d_in[13];
    const float* W2 = (const float*)d_in[14];
    const float* b2 = (const float*)d_in[15];
    float* out = (float*)d_out;

    const int SMEM_A = 4*64*FPH*2 + 256*4 + 68*XS*4;            // 45632
    const int SMEM_D = 3*64*FPH*2 + 192*4 + 68*XS*4;            // 36672

    if (g_s2 == nullptr) {
        cudaStreamCreateWithFlags(&g_s2, cudaStreamNonBlocking);
        cudaEventCreateWithFlags(&g_evFork, cudaEventDisableTiming);
        cudaEventCreateWithFlags(&g_evJoin, cudaEventDisableTiming);
        cudaFuncSetAttribute(qkv_kernel, cudaFuncAttributeMaxDynamicSharedMemorySize, SMEM_A);
        cudaFuncSetAttribute(gru_kernel, cudaFuncAttributeMaxDynamicSharedMemorySize, SMEM_D);
    }

    void* cnt_ptr = nullptr;
    cudaGetSymbolAddress(&cnt_ptr, g_cnt);

    // fork: CSR build chain on side stream, projections on main stream
    cudaEventRecord(g_evFork, 0);
    cudaStreamWaitEvent(g_s2, g_evFork, 0);

    cudaMemsetAsync(cnt_ptr, 0, Nn * sizeof(int), g_s2);
    hist_kernel<<<(Ee/4 + 255)/256, 256, 0, g_s2>>>(edst);
    scan_kernel<<<1, 1024, 0, g_s2>>>();
    scatter_kernel<<<(Ee/4 + 255)/256, 256, 0, g_s2>>>(edst, esrc);

    qkv_kernel<<<444, 256, SMEM_A>>>(inputs, state, Wq, bq, Wk, bk, Wv, bv, Ws, bs);

    // join
    cudaEventRecord(g_evJoin, g_s2);
    cudaStreamWaitEvent(0, g_evJoin, 0);

    // attention: one warp per (b, dst); writes h2 for masked nodes
    attn_kernel<<<(NODES*32 + 255)/256, 256>>>();

    // slim GRU (4 CTAs/SM)
    gru_kernel<<<444, 256, SMEM_D>>>(inputs, state, W1, b1, W2, b2, out);
}